// round 9
// baseline (speedup 1.0000x reference)
#include <cuda_runtime.h>
#include <cuda_bf16.h>
#include <cstdint>

// MoE gate hybrid (2-launch): HMMA bf16 3-term split GEMM (+inline W split)
// + softmax + top-8 + boundary flags; exact-fp32 fixup for flagged rows.
// r: (32768, 2048) fp32, W: (64, 2048) fp32, b: (64,) fp32
// out[0 .. B*64) = weights_hard ; out[B*64 .. 2*B*64) = weights_soft

#define D_DIM 2048
#define E_DIM 64
#define BM 128
#define BK 64
#define NCHUNKS (D_DIM / BK)     // 32
#define NTHREADS 256

#define APAD 72
#define AROWB (APAD * 2)         // 144 bytes

#define OFF_AHI 0                // 128*144 = 18432
#define OFF_ALO 18432
#define OFF_WHI 36864            // 64*144 = 9216
#define OFF_WLO 46080
#define OFF_BIAS 55296
#define SMEM_BYTES 55808
#define LPAD 68

// flag-gap margin: 40x over HMMA logit noise (~2e-5)
#define FLAG_MARGIN 8e-4f

__device__ int g_flag[32768];

__device__ __forceinline__ uint32_t smem_u32(const void* p) {
    uint32_t a;
    asm("{ .reg .u64 t; cvta.to.shared.u64 t, %1; cvt.u32.u64 %0, t; }" : "=r"(a) : "l"(p));
    return a;
}

__device__ __forceinline__ void ldmatrix_x4(uint32_t& r0, uint32_t& r1, uint32_t& r2, uint32_t& r3,
                                            uint32_t addr) {
    asm volatile("ldmatrix.sync.aligned.m8n8.x4.shared.b16 {%0,%1,%2,%3}, [%4];"
                 : "=r"(r0), "=r"(r1), "=r"(r2), "=r"(r3) : "r"(addr));
}

__device__ __forceinline__ void mma_bf16(float* d, const uint32_t* a, uint32_t b0, uint32_t b1) {
    asm volatile("mma.sync.aligned.m16n8k16.row.col.f32.bf16.bf16.f32 "
                 "{%0,%1,%2,%3}, {%4,%5,%6,%7}, {%8,%9}, {%0,%1,%2,%3};"
                 : "+f"(d[0]), "+f"(d[1]), "+f"(d[2]), "+f"(d[3])
                 : "r"(a[0]), "r"(a[1]), "r"(a[2]), "r"(a[3]), "r"(b0), "r"(b1));
}

// split one fp32 pair into bf16 hi/lo packed words
__device__ __forceinline__ void split2(float x, float y, uint32_t& hw, uint32_t& lw) {
    __nv_bfloat162 h = __floats2bfloat162_rn(x, y);
    float rx = x - __low2float(h);
    float ry = y - __high2float(h);
    __nv_bfloat162 l = __floats2bfloat162_rn(rx, ry);
    hw = *reinterpret_cast<uint32_t*>(&h);
    lw = *reinterpret_cast<uint32_t*>(&l);
}

// ---------------- main: HMMA GEMM (inline W split) + softmax + top8 + flags ----------------
__global__ __launch_bounds__(NTHREADS, 2)
void moe_gate_mma_kernel(const float* __restrict__ r,
                         const float* __restrict__ W,
                         const float* __restrict__ b,
                         float* __restrict__ out,
                         int B)
{
    extern __shared__ char smem[];
    const uint32_t sb = smem_u32(smem);

    const int tid = threadIdx.x;
    const int lane = tid & 31;
    const int warp = tid >> 5;

    float* bias_s = (float*)(smem + OFF_BIAS);
    if (tid < E_DIM) bias_s[tid] = b[tid];

    const float* Ag = r + (size_t)blockIdx.x * BM * D_DIM;

    // A global-load mapping: 2 threads per row, 8 float4 each
    const int arow = tid >> 1;
    const int acg = tid & 1;
    const float* Arow = Ag + (size_t)arow * D_DIM;

    const uint32_t sts_hi = sb + OFF_AHI + arow * AROWB + acg * 8;
    const uint32_t sts_lo = sb + OFF_ALO + arow * AROWB + acg * 8;

    // W fp32 load mapping: 4 threads per expert row, 4 float4 each
    const int wexp = tid >> 2;           // 0..63
    const int wq = tid & 3;              // quarter of 64 cols
    const float* Wrow = W + (size_t)wexp * D_DIM + wq * 16;
    const uint32_t wsts_hi = sb + OFF_WHI + wexp * AROWB + wq * 32;
    const uint32_t wsts_lo = sb + OFF_WLO + wexp * AROWB + wq * 32;

    // ldmatrix A: lane -> row = warp*16 + (lane&15), koff8 = lane>>4
    const uint32_t lda_hi = sb + OFF_AHI + (warp * 16 + (lane & 15)) * AROWB + (lane >> 4) * 16;
    const uint32_t lda_lo = lda_hi + (OFF_ALO - OFF_AHI);

    // ldmatrix B: lane -> n = (lane&7) + ((lane>>4)&1)*8, koff8 = (lane>>3)&1
    const uint32_t ldb_base = sb + OFF_WHI
        + ((lane & 7) + ((lane >> 4) & 1) * 8) * AROWB + ((lane >> 3) & 1) * 16;

    float4 regA[8];
#pragma unroll
    for (int i = 0; i < 8; ++i)
        regA[i] = *reinterpret_cast<const float4*>(Arow + (acg + 2 * i) * 4);

    float acc[8][4];
#pragma unroll
    for (int n = 0; n < 8; ++n)
#pragma unroll
        for (int j = 0; j < 4; ++j) acc[n][j] = 0.0f;

#pragma unroll 1
    for (int t = 0; t < NCHUNKS; ++t) {
        const int k0 = t * BK;
        __syncthreads();   // previous chunk's MMAs done reading smem

        // --- W fp32 chunk LDG (L2-hot), issued early to hide latency ---
        float4 wv[4];
#pragma unroll
        for (int i = 0; i < 4; ++i)
            wv[i] = *reinterpret_cast<const float4*>(Wrow + k0 + i * 4);

        // --- A: convert regs -> bf16 hi/lo, STS ---
#pragma unroll
        for (int i = 0; i < 8; ++i) {
            float4 v = regA[i];
            uint32_t h0, l0, h1, l1;
            split2(v.x, v.y, h0, l0);
            split2(v.z, v.w, h1, l1);
            uint32_t off = i * 16;
            asm volatile("st.shared.v2.b32 [%0], {%1,%2};" :: "r"(sts_hi + off), "r"(h0), "r"(h1));
            asm volatile("st.shared.v2.b32 [%0], {%1,%2};" :: "r"(sts_lo + off), "r"(l0), "r"(l1));
        }

        // --- prefetch next A chunk ---
        if (t < NCHUNKS - 1) {
#pragma unroll
            for (int i = 0; i < 8; ++i)
                regA[i] = *reinterpret_cast<const float4*>(Arow + k0 + BK + (acg + 2 * i) * 4);
        }

        // --- W: convert -> bf16 hi/lo, STS (16 floats -> 32B per plane) ---
        {
            uint32_t hw[8], lw[8];
#pragma unroll
            for (int i = 0; i < 4; ++i) {
                split2(wv[i].x, wv[i].y, hw[2 * i], lw[2 * i]);
                split2(wv[i].z, wv[i].w, hw[2 * i + 1], lw[2 * i + 1]);
            }
            asm volatile("st.shared.v4.b32 [%0], {%1,%2,%3,%4};"
                         :: "r"(wsts_hi), "r"(hw[0]), "r"(hw[1]), "r"(hw[2]), "r"(hw[3]));
            asm volatile("st.shared.v4.b32 [%0], {%1,%2,%3,%4};"
                         :: "r"(wsts_hi + 16), "r"(hw[4]), "r"(hw[5]), "r"(hw[6]), "r"(hw[7]));
            asm volatile("st.shared.v4.b32 [%0], {%1,%2,%3,%4};"
                         :: "r"(wsts_lo), "r"(lw[0]), "r"(lw[1]), "r"(lw[2]), "r"(lw[3]));
            asm volatile("st.shared.v4.b32 [%0], {%1,%2,%3,%4};"
                         :: "r"(wsts_lo + 16), "r"(lw[4]), "r"(lw[5]), "r"(lw[6]), "r"(lw[7]));
        }

        __syncthreads();

        // --- 96 MMAs: 4 k-steps x 4 ntile-pairs x (hh, hl, lh) ---
#pragma unroll
        for (int ks = 0; ks < 4; ++ks) {
            uint32_t ah[4], al[4];
            ldmatrix_x4(ah[0], ah[1], ah[2], ah[3], lda_hi + ks * 32);
            ldmatrix_x4(al[0], al[1], al[2], al[3], lda_lo + ks * 32);
#pragma unroll
            for (int ntp = 0; ntp < 4; ++ntp) {
                uint32_t bh0, bh1, bh2, bh3, bl0, bl1, bl2, bl3;
                uint32_t baddr = ldb_base + ntp * (16 * AROWB) + ks * 32;
                ldmatrix_x4(bh0, bh1, bh2, bh3, baddr);
                ldmatrix_x4(bl0, bl1, bl2, bl3, baddr + (OFF_WLO - OFF_WHI));
                mma_bf16(acc[2 * ntp], ah, bh0, bh1);
                mma_bf16(acc[2 * ntp], ah, bl0, bl1);
                mma_bf16(acc[2 * ntp], al, bh0, bh1);
                mma_bf16(acc[2 * ntp + 1], ah, bh2, bh3);
                mma_bf16(acc[2 * ntp + 1], ah, bl2, bl3);
                mma_bf16(acc[2 * ntp + 1], al, bh2, bh3);
            }
        }
    }

    // ---- spill logits to smem ----
    __syncthreads();
    float* Ls = (float*)smem;
    {
        int r0 = warp * 16 + (lane >> 2);
        int c0 = (lane & 3) * 2;
#pragma unroll
        for (int nt = 0; nt < 8; ++nt) {
            *reinterpret_cast<float2*>(&Ls[r0 * LPAD + nt * 8 + c0]) =
                make_float2(acc[nt][0], acc[nt][1]);
            *reinterpret_cast<float2*>(&Ls[(r0 + 8) * LPAD + nt * 8 + c0]) =
                make_float2(acc[nt][2], acc[nt][3]);
        }
    }
    __syncthreads();

    // ---- per-row softmax + top-8 + boundary flag ----
    if (tid < BM) {
        float lv[64];
        float m = -3.4e38f;
#pragma unroll
        for (int i = 0; i < 64; ++i) {
            lv[i] = Ls[tid * LPAD + i] + bias_s[i];
            m = fmaxf(m, lv[i]);
        }
        float sum = 0.0f;
#pragma unroll
        for (int i = 0; i < 64; ++i) { lv[i] = __expf(lv[i] - m); sum += lv[i]; }
        float inv = 1.0f / sum;
#pragma unroll
        for (int i = 0; i < 64; ++i) lv[i] *= inv;

        float thresh = 3.4e38f;
        float topsum = 0.0f;
#pragma unroll 1
        for (int tt = 0; tt < 8; ++tt) {
            float mm = -1.0f;
#pragma unroll
            for (int i = 0; i < 64; ++i) {
                float c = (lv[i] < thresh) ? lv[i] : -1.0f;
                mm = fmaxf(mm, c);
            }
            topsum += mm;
            thresh = mm;
        }
        // 9th-largest for the boundary-gap test
        float w9 = -1.0f;
#pragma unroll
        for (int i = 0; i < 64; ++i) {
            float c = (lv[i] < thresh) ? lv[i] : -1.0f;
            w9 = fmaxf(w9, c);
        }
        float rinv = 1.0f / (topsum + 1e-9f);

        size_t row = (size_t)blockIdx.x * BM + tid;
        g_flag[row] = (thresh - w9 < FLAG_MARGIN * thresh) ? 1 : 0;

        float* oH = out + row * E_DIM;
        float* oS = out + (size_t)B * E_DIM + row * E_DIM;
#pragma unroll
        for (int i = 0; i < 64; i += 4) {
            float4 s4 = make_float4(lv[i], lv[i + 1], lv[i + 2], lv[i + 3]);
            float4 h4 = make_float4(
                (lv[i] >= thresh) ? lv[i] * rinv : 0.0f,
                (lv[i + 1] >= thresh) ? lv[i + 1] * rinv : 0.0f,
                (lv[i + 2] >= thresh) ? lv[i + 2] * rinv : 0.0f,
                (lv[i + 3] >= thresh) ? lv[i + 3] * rinv : 0.0f);
            *reinterpret_cast<float4*>(oS + i) = s4;
            *reinterpret_cast<float4*>(oH + i) = h4;
        }
    }
}

// ---------------- fixup: exact fp32 recompute for flagged rows ----------------
__global__ __launch_bounds__(256)
void fixup_kernel(const float* __restrict__ r,
                  const float* __restrict__ W,
                  const float* __restrict__ b,
                  float* __restrict__ out,
                  int B)
{
    __shared__ float rrow[D_DIM];       // 8 KB
    __shared__ float logits[E_DIM];
    __shared__ float psm[E_DIM];
    __shared__ float scal[4];

    const int tid = threadIdx.x;

    // each block owns 128 consecutive rows
    for (int rr = 0; rr < 128; ++rr) {
        const int row = blockIdx.x * 128 + rr;
        if (!g_flag[row]) continue;   // uniform across block
        __syncthreads();

        for (int i = tid; i < D_DIM / 4; i += 256)
            reinterpret_cast<float4*>(rrow)[i] =
                reinterpret_cast<const float4*>(r + (size_t)row * D_DIM)[i];
        __syncthreads();

        const int e = tid >> 2;
        const int q = tid & 3;
        const float* Wr = W + (size_t)e * D_DIM + q * 512;
        const float* rq = rrow + q * 512;
        float s = 0.0f;
#pragma unroll 4
        for (int k = 0; k < 512; k += 4) {
            float4 wv = *reinterpret_cast<const float4*>(Wr + k);
            float4 rv = *reinterpret_cast<const float4*>(rq + k);
            s = fmaf(rv.x, wv.x, s);
            s = fmaf(rv.y, wv.y, s);
            s = fmaf(rv.z, wv.z, s);
            s = fmaf(rv.w, wv.w, s);
        }
        s += __shfl_xor_sync(0xffffffffu, s, 1);
        s += __shfl_xor_sync(0xffffffffu, s, 2);
        if (q == 0) logits[e] = s + b[e];
        __syncthreads();

        if (tid == 0) {
            float m = -3.4e38f;
            for (int i = 0; i < 64; ++i) m = fmaxf(m, logits[i]);
            float sum = 0.0f;
            for (int i = 0; i < 64; ++i) { psm[i] = __expf(logits[i] - m); sum += psm[i]; }
            float inv = 1.0f / sum;
            for (int i = 0; i < 64; ++i) psm[i] *= inv;
            float thresh = 3.4e38f;
            float topsum = 0.0f;
            for (int tt = 0; tt < 8; ++tt) {
                float mm = -1.0f;
                for (int i = 0; i < 64; ++i) {
                    float c = (psm[i] < thresh) ? psm[i] : -1.0f;
                    mm = fmaxf(mm, c);
                }
                topsum += mm;
                thresh = mm;
            }
            scal[2] = thresh;
            scal[3] = 1.0f / (topsum + 1e-9f);
        }
        __syncthreads();

        if (tid < E_DIM) {
            float p = psm[tid];
            float thresh = scal[2], rinv = scal[3];
            out[(size_t)B * E_DIM + (size_t)row * E_DIM + tid] = p;
            out[(size_t)row * E_DIM + tid] = (p >= thresh) ? p * rinv : 0.0f;
        }
    }
}

extern "C" void kernel_launch(void* const* d_in, const int* in_sizes, int n_in,
                              void* d_out, int out_size)
{
    const float* r = (const float*)d_in[0];
    const float* W = (const float*)d_in[1];
    const float* b = (const float*)d_in[2];
    float* out = (float*)d_out;
    int B = in_sizes[0] / D_DIM;

    cudaFuncSetAttribute(moe_gate_mma_kernel,
                         cudaFuncAttributeMaxDynamicSharedMemorySize, SMEM_BYTES);

    moe_gate_mma_kernel<<<B / BM, NTHREADS, SMEM_BYTES>>>(r, W, b, out, B);
    fixup_kernel<<<256, 256>>>(r, W, b, out, B);
}